// round 8
// baseline (speedup 1.0000x reference)
#include <cuda_runtime.h>
#include <cstdint>
#include <math.h>

#define GO_TAG 1
#define NEGV   -10000.0f
#define K_     64
#define MAXELEMS_ (1024u * 512u * 64u)

typedef unsigned long long ull;

// Scratch: alpha history rows 1..len-1 per batch, trans tables.
__device__ float g_trans[K_ * K_];    // trans[i][j] = score(i -> j)
__device__ float g_transT[K_ * K_];   // transT[j][i] = trans[i][j]
__device__ float g_alpha[MAXELEMS_];

__device__ __forceinline__ void cp_async16(uint32_t saddr, const void* gptr) {
    asm volatile("cp.async.ca.shared.global [%0], [%1], 16;"
                 :: "r"(saddr), "l"(gptr));
}
__device__ __forceinline__ void cp_commit() {
    asm volatile("cp.async.commit_group;");
}
template <int N>
__device__ __forceinline__ void cp_wait() {
    asm volatile("cp.async.wait_group %0;" :: "n"(N));
}

// Packed f32x2 add (Blackwell): two independent f32 adds in one instruction.
__device__ __forceinline__ ull add2(ull a, ull b) {
    ull d;
    asm("add.rn.f32x2 %0, %1, %2;" : "=l"(d) : "l"(a), "l"(b));
    return d;
}
__device__ __forceinline__ void unpack2(ull s, float& lo, float& hi) {
    asm("mov.b64 {%0, %1}, %2;" : "=f"(lo), "=f"(hi) : "l"(s));
}

// One Viterbi step for tag j: max_i(alpha[i] + tr[i][j]) + u, bit-exact.
// arow_sh: 64 old alphas in shared; ttr: 32 packed (tr[2q],tr[2q+1]) pairs.
__device__ __forceinline__ float vstep(const float* arow_sh,
                                       const ull* ttr, float u) {
    const ulonglong2* av = (const ulonglong2*)arow_sh;
    float ch[8];
    #pragma unroll
    for (int k = 0; k < 16; k++) {
        ulonglong2 p = av[k];
        ull s0 = add2(p.x, ttr[2 * k]);
        ull s1 = add2(p.y, ttr[2 * k + 1]);
        float l0, h0, l1, h1;
        unpack2(s0, l0, h0);
        unpack2(s1, l1, h1);
        const int c4 = (k & 1) * 4;
        if (k < 2) {
            ch[c4 + 0] = l0; ch[c4 + 1] = h0;
            ch[c4 + 2] = l1; ch[c4 + 3] = h1;
        } else {
            ch[c4 + 0] = fmaxf(ch[c4 + 0], l0);
            ch[c4 + 1] = fmaxf(ch[c4 + 1], h0);
            ch[c4 + 2] = fmaxf(ch[c4 + 2], l1);
            ch[c4 + 3] = fmaxf(ch[c4 + 3], h1);
        }
    }
    float m01 = fmaxf(ch[0], ch[1]);
    float m23 = fmaxf(ch[2], ch[3]);
    float m45 = fmaxf(ch[4], ch[5]);
    float m67 = fmaxf(ch[6], ch[7]);
    return fmaxf(fmaxf(m01, m23), fmaxf(m45, m67)) + u;
}

// ---------------------------------------------------------------------------
// Kernel 1: trans = log_softmax(A + mask * NEG, axis=-1) + transpose.
// ---------------------------------------------------------------------------
__global__ void __launch_bounds__(64)
trans_kernel(const float* __restrict__ c0, const float* __restrict__ c1) {
    __shared__ float  s_m[2];
    __shared__ double s_s[2];
    const int r = blockIdx.x;
    const int c = threadIdx.x;
    const int w = c >> 5;
    const int lane = c & 31;

    unsigned u0 = ((const unsigned*)c0)[r * K_ + c];
    const bool c0_is_mask = __syncthreads_and(u0 <= 1u);
    const int*   mask = (const int*)(c0_is_mask ? c0 : c1);
    const float* A    = c0_is_mask ? c1 : c0;

    float x = A[r * K_ + c] + (mask[r * K_ + c] ? NEGV : 0.0f);

    float m = x;
    #pragma unroll
    for (int d = 16; d > 0; d >>= 1) m = fmaxf(m, __shfl_xor_sync(~0u, m, d));
    if (lane == 0) s_m[w] = m;
    __syncthreads();
    m = fmaxf(s_m[0], s_m[1]);

    double e = exp((double)(x - m));
    #pragma unroll
    for (int d = 16; d > 0; d >>= 1) e += __shfl_xor_sync(~0u, e, d);
    if (lane == 0) s_s[w] = e;
    __syncthreads();
    const float l = (float)log(s_s[0] + s_s[1]);

    const float v = (x - m) - l;
    g_trans[r * K_ + c]  = v;
    g_transT[c * K_ + r] = v;
}

// ---------------------------------------------------------------------------
// Kernel 2: one 64-thread block processes TWO sequences in lockstep on a
// shared time counter (each seq's update uniformly guarded -> no waste).
// 2 independent dep chains per warp between barriers; single plain
// __syncthreads per step. Backward passes run in parallel (warp0=A, warp1=B).
// ---------------------------------------------------------------------------
__global__ void __launch_bounds__(64)
viterbi_kernel(const float* __restrict__ unary,
               const int* __restrict__ lengths,
               float* __restrict__ out,
               int T, int B) {
    __shared__ __align__(16) float s_transT[K_ * K_];
    __shared__ __align__(16) float s_alpha[2][2][K_];   // [seq][buf][j]
    __shared__ __align__(16) float s_u[2][2][8][K_];    // [seq][buf][s][j]
    __shared__ int s_last[2];

    const int j = threadIdx.x;
    const int bA = blockIdx.x * 2;
    const int bB = bA + 1;
    const bool liveB = (bB < B);

    const size_t bstride = (size_t)T * K_;

    int lenA = lengths[bA];
    lenA = lenA < 1 ? 1 : (lenA > T ? T : lenA);
    int lenB = 1;
    if (liveB) {
        lenB = lengths[bB];
        lenB = lenB < 1 ? 1 : (lenB > T ? T : lenB);
    }
    const int lenmax = lenA > lenB ? lenA : lenB;

    const float* uA = unary + (size_t)bA * bstride;
    const float* uB = unary + (size_t)(liveB ? bB : bA) * bstride;
    float* arA = g_alpha + (size_t)bA * bstride;
    float* arB = g_alpha + (size_t)(liveB ? bB : bA) * bstride;

    const uint32_t suA = (uint32_t)__cvta_generic_to_shared(&s_u[0][0][0][0]);
    const uint32_t suB = (uint32_t)__cvta_generic_to_shared(&s_u[1][0][0][0]);

    // ---- prefetch first chunks (steps 1..8 -> rows 0..7, clamped) ----
    {
        #pragma unroll
        for (int rr = 0; rr < 2; rr++) {
            int l = j + rr * 64;
            int s = l >> 4;
            int c = (l & 15) * 4;
            int row = s; if (row > T - 1) row = T - 1;
            cp_async16(suA + (uint32_t)(s * K_ + c) * 4, uA + (size_t)row * K_ + c);
            if (liveB)
                cp_async16(suB + (uint32_t)(s * K_ + c) * 4, uB + (size_t)row * K_ + c);
        }
        cp_commit();
    }

    // Shared transposed table (cooperative copy, 64 threads x 16 float4).
    {
        const float4* src = (const float4*)g_transT;
        float4* dst = (float4*)s_transT;
        #pragma unroll
        for (int q = 0; q < 16; q++) dst[j + q * 64] = src[j + q * 64];
    }

    // Transition column j packed over source-tag pairs (shared by both seqs).
    ull ttr[32];
    #pragma unroll
    for (int q = 0; q < 32; q++) {
        unsigned lo = __float_as_uint(g_trans[(2 * q) * K_ + j]);
        unsigned hi = __float_as_uint(g_trans[(2 * q + 1) * K_ + j]);
        ttr[q] = ((ull)hi << 32) | lo;
    }

    const float a0 = (j == GO_TAG) ? 0.0f : NEGV;
    s_alpha[0][0][j] = a0;
    s_alpha[1][0][j] = a0;
    __syncthreads();

    // -------------------- forward (shared time counter) --------------------
    int cbuf = 0;
    for (int t0 = 1; t0 <= lenmax; t0 += 8) {
        const bool pfA = (t0 + 8 <= lenA);
        const bool pfB = (t0 + 8 <= lenB);
        #pragma unroll
        for (int rr = 0; rr < 2; rr++) {
            int l = j + rr * 64;
            int s = l >> 4;
            int c = (l & 15) * 4;
            int row = t0 + 7 + s;
            if (row > T - 1) row = T - 1;
            uint32_t soff = (uint32_t)(((cbuf ^ 1) * 8 + s) * K_ + c) * 4;
            if (pfA) cp_async16(suA + soff, uA + (size_t)row * K_ + c);
            if (pfB) cp_async16(suB + soff, uB + (size_t)row * K_ + c);
        }
        cp_commit();
        cp_wait<1>();
        __syncthreads();

        #pragma unroll
        for (int s = 0; s < 8; s++) {
            const int t = t0 + s;
            if (t <= lenmax) {               // uniform per block
                if (t <= lenA) {             // uniform
                    float a = vstep(s_alpha[0][(t - 1) & 1], ttr,
                                    s_u[0][cbuf][s][j]);
                    s_alpha[0][t & 1][j] = a;
                    if (t < lenA) arA[(size_t)t * K_ + j] = a;
                }
                if (t <= lenB) {             // uniform
                    float a = vstep(s_alpha[1][(t - 1) & 1], ttr,
                                    s_u[1][cbuf][s][j]);
                    s_alpha[1][t & 1][j] = a;
                    if (t < lenB) arB[(size_t)t * K_ + j] = a;
                }
                __syncthreads();
            }
        }
        cbuf ^= 1;
    }

    // last = argmax (first-index tiebreak); thread 0 -> A, thread 32 -> B.
    if (j == 0 || j == 32) {
        const int g = j >> 5;
        const int len = g ? lenB : lenA;
        const float* af = s_alpha[g][len & 1];
        float bv = af[0];
        int bi = 0;
        #pragma unroll
        for (int i = 1; i < K_; i++) {
            if (af[i] > bv) { bv = af[i]; bi = i; }
        }
        s_last[g] = bi;
    }
    __syncthreads();

    // -------------------- tails + backward (warp g = seq g) ---------------
    {
        const int g = j >> 5;
        const int lane = j & 31;
        if (g == 0 || liveB) {
            const int len = g ? lenB : lenA;
            const int b = g ? bB : bA;
            float* arow = g ? arB : arA;
            const uint32_t su = g ? suB : suA;
            const int last = s_last[g];

            float* ob = out + (size_t)b * T;
            const float lastf = (float)last;
            for (int tau = (len - 1) + lane; tau < T; tau += 32) ob[tau] = lastf;

            if (len >= 2) {
                int tag = last;
                #pragma unroll
                for (int rr = 0; rr < 4; rr++) {
                    int l = lane + rr * 32;
                    int s = l >> 4;
                    int c = (l & 15) * 4;
                    int row = len - 1 - s; if (row < 0) row = 0;
                    cp_async16(su + (uint32_t)(s * K_ + c) * 4,
                               arow + (size_t)row * K_ + c);
                }
                cp_commit();

                int bbuf = 0;
                for (int tb = len; tb >= 2; tb -= 8) {
                    if (tb - 8 >= 2) {
                        #pragma unroll
                        for (int rr = 0; rr < 4; rr++) {
                            int l = lane + rr * 32;
                            int s = l >> 4;
                            int c = (l & 15) * 4;
                            int row = tb - 9 - s; if (row < 0) row = 0;
                            cp_async16(su + (uint32_t)(((bbuf ^ 1) * 8 + s) * K_ + c) * 4,
                                       arow + (size_t)row * K_ + c);
                        }
                    }
                    cp_commit();
                    cp_wait<1>();
                    __syncwarp();

                    const int tlo = (tb - 7 > 2) ? tb - 7 : 2;
                    #pragma unroll
                    for (int s = 0; s < 8; s++) {
                        const int t = tb - s;
                        if (t >= tlo) {
                            float2 a = ((const float2*)&s_u[g][bbuf][s][0])[lane];
                            float2 tt = ((const float2*)(s_transT + tag * K_))[lane];
                            float c0 = a.x + tt.x;
                            float c1 = a.y + tt.y;
                            float v; int li;
                            if (c0 >= c1) { v = c0; li = 2 * lane; }
                            else          { v = c1; li = 2 * lane + 1; }
                            unsigned bits = __float_as_uint(v);
                            unsigned key = ((int)bits < 0) ? ~bits
                                                           : (bits | 0x80000000u);
                            unsigned mx = __reduce_max_sync(0xffffffffu, key);
                            unsigned sel = (key == mx) ? (unsigned)(K_ - 1 - li) : 0u;
                            unsigned w = __reduce_max_sync(0xffffffffu, sel);
                            tag = (K_ - 1) - (int)w;
                            if (lane == 0) ob[t - 2] = (float)tag;
                        }
                    }
                    bbuf ^= 1;
                }
            }
        }
    }
}

extern "C" void kernel_launch(void* const* d_in, const int* in_sizes, int n_in,
                              void* d_out, int out_size) {
    // ----- identify inputs by SIZE, not position -----
    int iu = 0;
    for (int i = 1; i < n_in; i++)
        if (in_sizes[i] > in_sizes[iu]) iu = i;

    int pair[2] = {-1, -1};
    int ilen = -1;
    for (int i = 0; i < n_in; i++) {
        if (i == iu) continue;
        for (int k = 0; k < n_in; k++) {
            if (k == i || k == iu) continue;
            if (in_sizes[k] == in_sizes[i]) { pair[0] = i < k ? i : k; pair[1] = i < k ? k : i; }
        }
    }
    for (int i = 0; i < n_in; i++)
        if (i != iu && i != pair[0] && i != pair[1]) ilen = i;
    if (ilen < 0) { iu = 0; ilen = 1; pair[0] = 2; pair[1] = 3; }

    const float* unary   = (const float*)d_in[iu];
    const int*   lengths = (const int*)d_in[ilen];
    const float* c0      = (const float*)d_in[pair[0]];
    const float* c1      = (const float*)d_in[pair[1]];
    float* out = (float*)d_out;

    const int B = in_sizes[ilen];
    const int T = (int)((long long)in_sizes[iu] / ((long long)B * K_));

    trans_kernel<<<K_, K_>>>(c0, c1);
    viterbi_kernel<<<(B + 1) / 2, 64>>>(unary, lengths, out, T, B);
}